// round 4
// baseline (speedup 1.0000x reference)
#include <cuda_runtime.h>

#define NN 4096
#define EE 3
#define TT 5
#define DDIM 4
#define FF 64
#define HH 64
#define BB 2
#define PSTEPS 10
#define NC 8   // B*D columns of the skinny GEMM

// Persistent scratch (fully rewritten every launch -> deterministic)
__device__ __align__(16) float g_win[TT][NN][NC];       // [slot][n][b*4+d]
__device__ __align__(16) float g_PW [TT][EE][NN][NC];   // [slot][e][n][b*4+d] = A_e @ win_slot
__device__ __align__(16) float g_rowsum[EE][NN];
__device__ int g_mask[NN];

// ---------------------------------------------------------------------------
// Init: scatter time_segs [B,T,N,D] into window slots; zero mask.
// ---------------------------------------------------------------------------
__global__ void k_init(const float* __restrict__ ts) {
  int i = blockIdx.x * blockDim.x + threadIdx.x;
  if (i < NN) g_mask[i] = 0;
  if (i < BB * TT * NN * DDIM) {
    int d  = i & 3;
    int n  = (i >> 2) & (NN - 1);
    int bt = i >> 14;          // b*5 + t
    int t  = bt % 5;
    int b  = bt / 5;
    g_win[t][n][b * 4 + d] = ts[i];
  }
}

// ---------------------------------------------------------------------------
// Node mask: column-any over all (e,row). adjs >= 0 so (sum>0) == (any>0).
// grid = 32 col-tiles * 48 row-chunks, block = 128. Coalesced row reads.
// ---------------------------------------------------------------------------
__global__ void __launch_bounds__(128) k_mask(const float* __restrict__ A) {
  int m     = (blockIdx.x & 31) * 128 + threadIdx.x;
  int chunk = blockIdx.x >> 5;                    // 0..47, 256 rows each
  const float* p = A + (size_t)chunk * 256 * NN + m;
  int any = 0;
#pragma unroll 8
  for (int r = 0; r < 256; r++)
    any |= (p[(size_t)r * NN] > 0.0f) ? 1 : 0;
  if (any) atomicOr(&g_mask[m], 1);
}

// ---------------------------------------------------------------------------
// Tall-skinny GEMM: g_PW[slot][e][n][c] = sum_m A[e][n][m] * g_win[slot][m][c]
// HBM-bound stream of A. block=128 (4 warps), warp owns 8 rows, lanes split m.
// X tile (1024 m x 8 c) staged transposed in SMEM. Optional exact row sums.
// grid = EE*128.
// ---------------------------------------------------------------------------
template <bool RS>
__global__ void __launch_bounds__(128) k_gemm(const float* __restrict__ A, int slot) {
  __shared__ float XT[8][1024];
  const float* X = &g_win[slot][0][0];

  int e    = blockIdx.x >> 7;
  int tile = blockIdx.x & 127;
  int warp = threadIdx.x >> 5, lane = threadIdx.x & 31;
  int row0 = tile * 32 + warp * 8;
  const float* Ab = A + (size_t)e * NN * NN + (size_t)row0 * NN;

  float acc[8][8];
  float rs[8];
#pragma unroll
  for (int r = 0; r < 8; r++) {
    rs[r] = 0.f;
#pragma unroll
    for (int c = 0; c < 8; c++) acc[r][c] = 0.f;
  }

  for (int t0 = 0; t0 < NN; t0 += 1024) {
    __syncthreads();
    const float4* X4 = (const float4*)(X + (size_t)t0 * NC);
    for (int i = threadIdx.x; i < 2048; i += 128) {
      float4 v = X4[i];
      int m = i >> 1, c0 = (i & 1) * 4;
      XT[c0 + 0][m] = v.x; XT[c0 + 1][m] = v.y;
      XT[c0 + 2][m] = v.z; XT[c0 + 3][m] = v.w;
    }
    __syncthreads();

    const float* Ap = Ab + t0 + lane;
#pragma unroll 4
    for (int mb = 0; mb < 1024; mb += 32) {
      int m = mb + lane;
      float x0 = XT[0][m], x1 = XT[1][m], x2 = XT[2][m], x3 = XT[3][m];
      float x4 = XT[4][m], x5 = XT[5][m], x6 = XT[6][m], x7 = XT[7][m];
#pragma unroll
      for (int r = 0; r < 8; r++) {
        float a = Ap[(size_t)r * NN + mb];
        acc[r][0] += a * x0; acc[r][1] += a * x1;
        acc[r][2] += a * x2; acc[r][3] += a * x3;
        acc[r][4] += a * x4; acc[r][5] += a * x5;
        acc[r][6] += a * x6; acc[r][7] += a * x7;
        if (RS) rs[r] += a;
      }
    }
  }

  // deterministic butterfly reduction across lanes
#pragma unroll
  for (int r = 0; r < 8; r++) {
#pragma unroll
    for (int c = 0; c < 8; c++) {
      float v = acc[r][c];
#pragma unroll
      for (int off = 16; off; off >>= 1) v += __shfl_xor_sync(0xffffffffu, v, off);
      acc[r][c] = v;
    }
    if (RS) {
      float v = rs[r];
#pragma unroll
      for (int off = 16; off; off >>= 1) v += __shfl_xor_sync(0xffffffffu, v, off);
      rs[r] = v;
    }
  }
  if (lane == 0) {
#pragma unroll
    for (int r = 0; r < 8; r++) {
      float4* o = (float4*)&g_PW[slot][e][row0 + r][0];
      o[0] = make_float4(acc[r][0], acc[r][1], acc[r][2], acc[r][3]);
      o[1] = make_float4(acc[r][4], acc[r][5], acc[r][6], acc[r][7]);
      if (RS) g_rowsum[e][row0 + r] = rs[r];
    }
  }
}

// ---------------------------------------------------------------------------
// Fused per-node step. block = 128 (4 warps), each warp handles 4 (b,n)
// instances independently (only __syncwarp, no block barriers).
// Lane owns channel pair {lane, lane+32}. grid = 8192/16 = 512.
// ---------------------------------------------------------------------------
__global__ void __launch_bounds__(128) k_step(
    const float* __restrict__ conv_w, const float* __restrict__ conv_b,
    const float* __restrict__ enc_w1, const float* __restrict__ enc_w2,
    const float* __restrict__ enc_b,  const float* __restrict__ dec_w,
    const float* __restrict__ dec_b,  const float* __restrict__ out_w,
    const float* __restrict__ out_b,  float* __restrict__ dout, int s)
{
  __shared__ __align__(16) float s_win[4][4][20];
  __shared__ __align__(16) float s_pw [4][4][60];
  __shared__ float s_cond[4][4][64];
  __shared__ float s_agg [4][4][192];
  __shared__ float s_enc [4][4][64];

  int warp = threadIdx.x >> 5, lane = threadIdx.x & 31;
  int base = blockIdx.x * 16 + warp * 4;

  // ---- stage window + PW values for this warp's 4 instances ----
  for (int j = lane; j < 80; j += 32) {
    int li = j / 20, k = j % 20;
    int inst = base + li;
    int b = inst >> 12, n = inst & (NN - 1);
    if (k < 5) {
      int slotv = (s + k) % 5;
      float4 v = *(const float4*)&g_win[slotv][n][b * 4];
      *(float4*)&s_win[warp][li][k * 4] = v;
    } else {
      int k2 = k - 5, e = k2 / 5, t = k2 % 5;
      int slotv = (s + t) % 5;
      float4 v = *(const float4*)&g_PW[slotv][e][n][b * 4];
      *(float4*)&s_pw[warp][li][e * 20 + t * 4] = v;
    }
  }
  __syncwarp();

  int nn[4];
#pragma unroll
  for (int i = 0; i < 4; i++) nn[i] = (base + i) & (NN - 1);

  // ---- cond + agg (20 -> 64 contractions) ----
  float cb0 = conv_b[lane], cb1 = conv_b[lane + 32];
  float cond[4][2], agg[4][3][2];
#pragma unroll
  for (int i = 0; i < 4; i++) {
    cond[i][0] = cb0; cond[i][1] = cb1;
#pragma unroll
    for (int e = 0; e < 3; e++) {
      float r = g_rowsum[e][nn[i]];
      agg[i][e][0] = r * cb0; agg[i][e][1] = r * cb1;
    }
  }
  for (int td = 0; td < 20; td++) {
    float cw0 = conv_w[td * 64 + lane];
    float cw1 = conv_w[td * 64 + lane + 32];
#pragma unroll
    for (int i = 0; i < 4; i++) {
      float w = s_win[warp][i][td];
      cond[i][0] += w * cw0; cond[i][1] += w * cw1;
#pragma unroll
      for (int e = 0; e < 3; e++) {
        float a = s_pw[warp][i][e * 20 + td];
        agg[i][e][0] += a * cw0; agg[i][e][1] += a * cw1;
      }
    }
  }
#pragma unroll
  for (int i = 0; i < 4; i++) {
    s_cond[warp][i][lane] = cond[i][0];
    s_cond[warp][i][lane + 32] = cond[i][1];
#pragma unroll
    for (int e = 0; e < 3; e++) {
      s_agg[warp][i][e * 64 + lane] = agg[i][e][0];
      s_agg[warp][i][e * 64 + lane + 32] = agg[i][e][1];
    }
  }
  __syncwarp();

  // ---- per-edge-type GCSConv + tanh stack ----
  float encs[4][2];
#pragma unroll
  for (int i = 0; i < 4; i++) { encs[i][0] = 0.f; encs[i][1] = 0.f; }
  for (int e = 0; e < 3; e++) {
    float acc[4][2];
    float eb0 = enc_b[e * 64 + lane], eb1 = enc_b[e * 64 + lane + 32];
#pragma unroll
    for (int i = 0; i < 4; i++) { acc[i][0] = eb0; acc[i][1] = eb1; }
    for (int f = 0; f < 64; f++) {
      int wi = (e * 64 + f) * 64;
      float w10 = enc_w1[wi + lane], w11 = enc_w1[wi + lane + 32];
      float w20 = enc_w2[wi + lane], w21 = enc_w2[wi + lane + 32];
#pragma unroll
      for (int i = 0; i < 4; i++) {
        float a = s_agg[warp][i][e * 64 + f];
        float c = s_cond[warp][i][f];
        acc[i][0] += a * w10 + c * w20;
        acc[i][1] += a * w11 + c * w21;
      }
    }
#pragma unroll
    for (int i = 0; i < 4; i++) {
      encs[i][0] += tanhf(acc[i][0]);
      encs[i][1] += tanhf(acc[i][1]);
    }
  }
#pragma unroll
  for (int i = 0; i < 4; i++) {
    float mk = g_mask[nn[i]] ? 1.0f : 0.0f;
    s_enc[warp][i][lane]      = tanhf(encs[i][0]) * mk;
    s_enc[warp][i][lane + 32] = tanhf(encs[i][1]) * mk;
  }
  __syncwarp();

  // ---- decoder: relu([cond, enc] @ dec_w + dec_b) ----
  float hh[4][2];
  float db0 = dec_b[lane], db1 = dec_b[lane + 32];
#pragma unroll
  for (int i = 0; i < 4; i++) { hh[i][0] = db0; hh[i][1] = db1; }
  for (int k = 0; k < 64; k++) {
    float dw0 = dec_w[k * 64 + lane], dw1 = dec_w[k * 64 + lane + 32];
#pragma unroll
    for (int i = 0; i < 4; i++) {
      float x = s_cond[warp][i][k];
      hh[i][0] += x * dw0; hh[i][1] += x * dw1;
    }
  }
  for (int k = 0; k < 64; k++) {
    float dw0 = dec_w[(64 + k) * 64 + lane], dw1 = dec_w[(64 + k) * 64 + lane + 32];
#pragma unroll
    for (int i = 0; i < 4; i++) {
      float x = s_enc[warp][i][k];
      hh[i][0] += x * dw0; hh[i][1] += x * dw1;
    }
  }
#pragma unroll
  for (int i = 0; i < 4; i++) {
    hh[i][0] = fmaxf(hh[i][0], 0.f);
    hh[i][1] = fmaxf(hh[i][1], 0.f);
  }

  // ---- output projection + residual + window update ----
  float4 owa = *(const float4*)&out_w[lane * 4];
  float4 owb = *(const float4*)&out_w[(lane + 32) * 4];
  float ob0 = out_b[0], ob1 = out_b[1], ob2 = out_b[2], ob3 = out_b[3];
  int slot_new = s % 5;
#pragma unroll
  for (int i = 0; i < 4; i++) {
    float p0 = hh[i][0] * owa.x + hh[i][1] * owb.x;
    float p1 = hh[i][0] * owa.y + hh[i][1] * owb.y;
    float p2 = hh[i][0] * owa.z + hh[i][1] * owb.z;
    float p3 = hh[i][0] * owa.w + hh[i][1] * owb.w;
#pragma unroll
    for (int off = 16; off; off >>= 1) {
      p0 += __shfl_xor_sync(0xffffffffu, p0, off);
      p1 += __shfl_xor_sync(0xffffffffu, p1, off);
      p2 += __shfl_xor_sync(0xffffffffu, p2, off);
      p3 += __shfl_xor_sync(0xffffffffu, p3, off);
    }
    if (lane == 0) {
      int inst = base + i;
      int b = inst >> 12, n = inst & (NN - 1);
      float4 o;
      o.x = s_win[warp][i][16] + tanhf(p0 + ob0);
      o.y = s_win[warp][i][17] + tanhf(p1 + ob1);
      o.z = s_win[warp][i][18] + tanhf(p2 + ob2);
      o.w = s_win[warp][i][19] + tanhf(p3 + ob3);
      *(float4*)&g_win[slot_new][n][b * 4] = o;
      *(float4*)&dout[(size_t)((b * PSTEPS + s) * NN + n) * 4] = o;
    }
  }
}

// ---------------------------------------------------------------------------
extern "C" void kernel_launch(void* const* d_in, const int* in_sizes, int n_in,
                              void* d_out, int out_size) {
  const float* ts     = (const float*)d_in[0];
  const float* A      = (const float*)d_in[1];
  const float* conv_w = (const float*)d_in[2];
  const float* conv_b = (const float*)d_in[3];
  const float* enc_w1 = (const float*)d_in[4];
  const float* enc_w2 = (const float*)d_in[5];
  const float* enc_b  = (const float*)d_in[6];
  const float* dec_w  = (const float*)d_in[7];
  const float* dec_b  = (const float*)d_in[8];
  const float* out_w  = (const float*)d_in[9];
  const float* out_b  = (const float*)d_in[10];
  float* out = (float*)d_out;

  k_init<<<640, 256>>>(ts);
  k_mask<<<1536, 128>>>(A);
  k_gemm<true><<<EE * 128, 128>>>(A, 0);
  for (int t = 1; t < TT; t++)
    k_gemm<false><<<EE * 128, 128>>>(A, t);

  for (int s = 0; s < PSTEPS; s++) {
    k_step<<<512, 128>>>(conv_w, conv_b, enc_w1, enc_w2, enc_b,
                         dec_w, dec_b, out_w, out_b, out, s);
    if (s < PSTEPS - 1)
      k_gemm<false><<<EE * 128, 128>>>(A, s % 5);
  }
}

// round 6
// speedup vs baseline: 2.2873x; 2.2873x over previous
#include <cuda_runtime.h>

#define NN 4096
#define EE 3
#define TT 5
#define DDIM 4
#define FF 64
#define HH 64
#define BB 2
#define PSTEPS 10
#define NC 8   // B*D columns of the skinny GEMM

// Persistent scratch (fully rewritten every launch -> deterministic)
__device__ __align__(16) float g_win[TT][NN][NC];       // [slot][n][b*4+d]
__device__ __align__(16) float g_PW [TT][EE][NN][NC];   // [slot][e][n][b*4+d] = A_e @ win_slot
__device__ __align__(16) float g_rowsum[EE][NN];
__device__ int g_mask[NN];

// ---------------------------------------------------------------------------
// Init: scatter time_segs [B,T,N,D] into window slots; zero mask.
// ---------------------------------------------------------------------------
__global__ void k_init(const float* __restrict__ ts) {
  int i = blockIdx.x * blockDim.x + threadIdx.x;
  if (i < NN) g_mask[i] = 0;
  if (i < BB * TT * NN * DDIM) {
    int d  = i & 3;
    int n  = (i >> 2) & (NN - 1);
    int bt = i >> 14;          // b*5 + t
    int t  = bt % 5;
    int b  = bt / 5;
    g_win[t][n][b * 4 + d] = ts[i];
  }
}

// ---------------------------------------------------------------------------
// Tall-skinny GEMM: g_PW[slot][e][n][c] = sum_m A[e][n][m] * g_win[slot][m][c]
// HBM-streaming of A via float4 + __ldcs. block = 128 (4 warps), warp owns
// 4 rows, lanes split m in quads. X tile (1024 m x 8 c) staged transposed in
// SMEM as float4 planes -> conflict-free LDS.128. grid = EE * 256.
// RS pass additionally produces exact row sums and the column-any node mask
// (same-value global stores -> race-safe & deterministic).
// ---------------------------------------------------------------------------
template <bool RS>
__global__ void __launch_bounds__(128, 4) k_gemm(const float* __restrict__ A, int slot) {
  __shared__ float4 XT[8][256];            // XT[c][mq] = x[c][4mq .. 4mq+3]
  __shared__ unsigned s_any[4][256];       // per-warp column-any (RS pass)

  const float* X = &g_win[slot][0][0];
  int e    = blockIdx.x >> 8;
  int tile = blockIdx.x & 255;
  int warp = threadIdx.x >> 5, lane = threadIdx.x & 31;
  int row0 = tile * 16 + warp * 4;

  const float* Ab0 = A + (size_t)e * NN * NN + (size_t)(row0 + 0) * NN;
  const float* Ab1 = Ab0 + NN;
  const float* Ab2 = Ab1 + NN;
  const float* Ab3 = Ab2 + NN;

  float acc[4][8];
  float rs[4];
#pragma unroll
  for (int r = 0; r < 4; r++) {
    rs[r] = 0.f;
#pragma unroll
    for (int c = 0; c < 8; c++) acc[r][c] = 0.f;
  }

  float* XTs = (float*)XT;

  for (int t0 = 0; t0 < NN; t0 += 1024) {
    __syncthreads();
    // stage X tile transposed: XTs[c*1024 + m] = X[t0+m][c]
    const float4* X4 = (const float4*)(X + (size_t)t0 * NC);
    for (int i = threadIdx.x; i < 2048; i += 128) {
      float4 v = X4[i];
      int m = i >> 1, c0 = (i & 1) * 4;
      XTs[(c0 + 0) * 1024 + m] = v.x;
      XTs[(c0 + 1) * 1024 + m] = v.y;
      XTs[(c0 + 2) * 1024 + m] = v.z;
      XTs[(c0 + 3) * 1024 + m] = v.w;
    }
    __syncthreads();

    const float4* A0 = (const float4*)(Ab0 + t0);
    const float4* A1 = (const float4*)(Ab1 + t0);
    const float4* A2 = (const float4*)(Ab2 + t0);
    const float4* A3 = (const float4*)(Ab3 + t0);

#pragma unroll 2
    for (int it = 0; it < 8; it++) {
      int mq = it * 32 + lane;
      float4 a0 = __ldcs(A0 + mq);
      float4 a1 = __ldcs(A1 + mq);
      float4 a2 = __ldcs(A2 + mq);
      float4 a3 = __ldcs(A3 + mq);

      if (RS) {
        rs[0] += (a0.x + a0.y) + (a0.z + a0.w);
        rs[1] += (a1.x + a1.y) + (a1.z + a1.w);
        rs[2] += (a2.x + a2.y) + (a2.z + a2.w);
        rs[3] += (a3.x + a3.y) + (a3.z + a3.w);
        unsigned v = 0;
        if (a0.x > 0.f || a1.x > 0.f || a2.x > 0.f || a3.x > 0.f) v |= 0x1u;
        if (a0.y > 0.f || a1.y > 0.f || a2.y > 0.f || a3.y > 0.f) v |= 0x100u;
        if (a0.z > 0.f || a1.z > 0.f || a2.z > 0.f || a3.z > 0.f) v |= 0x10000u;
        if (a0.w > 0.f || a1.w > 0.f || a2.w > 0.f || a3.w > 0.f) v |= 0x1000000u;
        s_any[warp][mq] = v;   // every mq written once per warp per tile
      }

#pragma unroll
      for (int c = 0; c < 8; c++) {
        float4 x = XT[c][mq];
        acc[0][c] = fmaf(a0.w, x.w, fmaf(a0.z, x.z, fmaf(a0.y, x.y, fmaf(a0.x, x.x, acc[0][c]))));
        acc[1][c] = fmaf(a1.w, x.w, fmaf(a1.z, x.z, fmaf(a1.y, x.y, fmaf(a1.x, x.x, acc[1][c]))));
        acc[2][c] = fmaf(a2.w, x.w, fmaf(a2.z, x.z, fmaf(a2.y, x.y, fmaf(a2.x, x.x, acc[2][c]))));
        acc[3][c] = fmaf(a3.w, x.w, fmaf(a3.z, x.z, fmaf(a3.y, x.y, fmaf(a3.x, x.x, acc[3][c]))));
      }
    }

    if (RS) {
      __syncthreads();  // all warps' s_any for this tile complete
      for (int i = threadIdx.x; i < 256; i += 128) {
        unsigned v = s_any[0][i] | s_any[1][i] | s_any[2][i] | s_any[3][i];
        int mg = t0 + i * 4;
        if (v & 0x1u)        g_mask[mg + 0] = 1;   // same-value store: race-safe
        if (v & 0x100u)      g_mask[mg + 1] = 1;
        if (v & 0x10000u)    g_mask[mg + 2] = 1;
        if (v & 0x1000000u)  g_mask[mg + 3] = 1;
      }
    }
  }

  // deterministic butterfly reduction across lanes
#pragma unroll
  for (int r = 0; r < 4; r++) {
#pragma unroll
    for (int c = 0; c < 8; c++) {
      float v = acc[r][c];
#pragma unroll
      for (int off = 16; off; off >>= 1) v += __shfl_xor_sync(0xffffffffu, v, off);
      acc[r][c] = v;
    }
    if (RS) {
      float v = rs[r];
#pragma unroll
      for (int off = 16; off; off >>= 1) v += __shfl_xor_sync(0xffffffffu, v, off);
      rs[r] = v;
    }
  }
  if (lane == 0) {
#pragma unroll
    for (int r = 0; r < 4; r++) {
      float4* o = (float4*)&g_PW[slot][e][row0 + r][0];
      o[0] = make_float4(acc[r][0], acc[r][1], acc[r][2], acc[r][3]);
      o[1] = make_float4(acc[r][4], acc[r][5], acc[r][6], acc[r][7]);
      if (RS) g_rowsum[e][row0 + r] = rs[r];
    }
  }
}

// ---------------------------------------------------------------------------
// Fused per-node step. block = 128 (4 warps), each warp handles 4 (b,n)
// instances independently (only __syncwarp, no block barriers).
// Lane owns channel pair {lane, lane+32}. grid = 8192/16 = 512.
// ---------------------------------------------------------------------------
__global__ void __launch_bounds__(128) k_step(
    const float* __restrict__ conv_w, const float* __restrict__ conv_b,
    const float* __restrict__ enc_w1, const float* __restrict__ enc_w2,
    const float* __restrict__ enc_b,  const float* __restrict__ dec_w,
    const float* __restrict__ dec_b,  const float* __restrict__ out_w,
    const float* __restrict__ out_b,  float* __restrict__ dout, int s)
{
  __shared__ __align__(16) float s_win[4][4][20];
  __shared__ __align__(16) float s_pw [4][4][60];
  __shared__ float s_cond[4][4][64];
  __shared__ float s_agg [4][4][192];
  __shared__ float s_enc [4][4][64];

  int warp = threadIdx.x >> 5, lane = threadIdx.x & 31;
  int base = blockIdx.x * 16 + warp * 4;

  // ---- stage window + PW values for this warp's 4 instances ----
  for (int j = lane; j < 80; j += 32) {
    int li = j / 20, k = j % 20;
    int inst = base + li;
    int b = inst >> 12, n = inst & (NN - 1);
    if (k < 5) {
      int slotv = (s + k) % 5;
      float4 v = *(const float4*)&g_win[slotv][n][b * 4];
      *(float4*)&s_win[warp][li][k * 4] = v;
    } else {
      int k2 = k - 5, e = k2 / 5, t = k2 % 5;
      int slotv = (s + t) % 5;
      float4 v = *(const float4*)&g_PW[slotv][e][n][b * 4];
      *(float4*)&s_pw[warp][li][e * 20 + t * 4] = v;
    }
  }
  __syncwarp();

  int nn[4];
#pragma unroll
  for (int i = 0; i < 4; i++) nn[i] = (base + i) & (NN - 1);

  // ---- cond + agg (20 -> 64 contractions) ----
  float cb0 = conv_b[lane], cb1 = conv_b[lane + 32];
  float cond[4][2], agg[4][3][2];
#pragma unroll
  for (int i = 0; i < 4; i++) {
    cond[i][0] = cb0; cond[i][1] = cb1;
#pragma unroll
    for (int e = 0; e < 3; e++) {
      float r = g_rowsum[e][nn[i]];
      agg[i][e][0] = r * cb0; agg[i][e][1] = r * cb1;
    }
  }
  for (int td = 0; td < 20; td++) {
    float cw0 = conv_w[td * 64 + lane];
    float cw1 = conv_w[td * 64 + lane + 32];
#pragma unroll
    for (int i = 0; i < 4; i++) {
      float w = s_win[warp][i][td];
      cond[i][0] += w * cw0; cond[i][1] += w * cw1;
#pragma unroll
      for (int e = 0; e < 3; e++) {
        float a = s_pw[warp][i][e * 20 + td];
        agg[i][e][0] += a * cw0; agg[i][e][1] += a * cw1;
      }
    }
  }
#pragma unroll
  for (int i = 0; i < 4; i++) {
    s_cond[warp][i][lane] = cond[i][0];
    s_cond[warp][i][lane + 32] = cond[i][1];
#pragma unroll
    for (int e = 0; e < 3; e++) {
      s_agg[warp][i][e * 64 + lane] = agg[i][e][0];
      s_agg[warp][i][e * 64 + lane + 32] = agg[i][e][1];
    }
  }
  __syncwarp();

  // ---- per-edge-type GCSConv + tanh stack ----
  float encs[4][2];
#pragma unroll
  for (int i = 0; i < 4; i++) { encs[i][0] = 0.f; encs[i][1] = 0.f; }
  for (int e = 0; e < 3; e++) {
    float acc[4][2];
    float eb0 = enc_b[e * 64 + lane], eb1 = enc_b[e * 64 + lane + 32];
#pragma unroll
    for (int i = 0; i < 4; i++) { acc[i][0] = eb0; acc[i][1] = eb1; }
    for (int f = 0; f < 64; f++) {
      int wi = (e * 64 + f) * 64;
      float w10 = enc_w1[wi + lane], w11 = enc_w1[wi + lane + 32];
      float w20 = enc_w2[wi + lane], w21 = enc_w2[wi + lane + 32];
#pragma unroll
      for (int i = 0; i < 4; i++) {
        float a = s_agg[warp][i][e * 64 + f];
        float c = s_cond[warp][i][f];
        acc[i][0] += a * w10 + c * w20;
        acc[i][1] += a * w11 + c * w21;
      }
    }
#pragma unroll
    for (int i = 0; i < 4; i++) {
      encs[i][0] += tanhf(acc[i][0]);
      encs[i][1] += tanhf(acc[i][1]);
    }
  }
#pragma unroll
  for (int i = 0; i < 4; i++) {
    float mk = g_mask[nn[i]] ? 1.0f : 0.0f;
    s_enc[warp][i][lane]      = tanhf(encs[i][0]) * mk;
    s_enc[warp][i][lane + 32] = tanhf(encs[i][1]) * mk;
  }
  __syncwarp();

  // ---- decoder: relu([cond, enc] @ dec_w + dec_b) ----
  float hh[4][2];
  float db0 = dec_b[lane], db1 = dec_b[lane + 32];
#pragma unroll
  for (int i = 0; i < 4; i++) { hh[i][0] = db0; hh[i][1] = db1; }
  for (int k = 0; k < 64; k++) {
    float dw0 = dec_w[k * 64 + lane], dw1 = dec_w[k * 64 + lane + 32];
#pragma unroll
    for (int i = 0; i < 4; i++) {
      float x = s_cond[warp][i][k];
      hh[i][0] += x * dw0; hh[i][1] += x * dw1;
    }
  }
  for (int k = 0; k < 64; k++) {
    float dw0 = dec_w[(64 + k) * 64 + lane], dw1 = dec_w[(64 + k) * 64 + lane + 32];
#pragma unroll
    for (int i = 0; i < 4; i++) {
      float x = s_enc[warp][i][k];
      hh[i][0] += x * dw0; hh[i][1] += x * dw1;
    }
  }
#pragma unroll
  for (int i = 0; i < 4; i++) {
    hh[i][0] = fmaxf(hh[i][0], 0.f);
    hh[i][1] = fmaxf(hh[i][1], 0.f);
  }

  // ---- output projection + residual + window update ----
  float4 owa = *(const float4*)&out_w[lane * 4];
  float4 owb = *(const float4*)&out_w[(lane + 32) * 4];
  float ob0 = out_b[0], ob1 = out_b[1], ob2 = out_b[2], ob3 = out_b[3];
  int slot_new = s % 5;
#pragma unroll
  for (int i = 0; i < 4; i++) {
    float p0 = hh[i][0] * owa.x + hh[i][1] * owb.x;
    float p1 = hh[i][0] * owa.y + hh[i][1] * owb.y;
    float p2 = hh[i][0] * owa.z + hh[i][1] * owb.z;
    float p3 = hh[i][0] * owa.w + hh[i][1] * owb.w;
#pragma unroll
    for (int off = 16; off; off >>= 1) {
      p0 += __shfl_xor_sync(0xffffffffu, p0, off);
      p1 += __shfl_xor_sync(0xffffffffu, p1, off);
      p2 += __shfl_xor_sync(0xffffffffu, p2, off);
      p3 += __shfl_xor_sync(0xffffffffu, p3, off);
    }
    if (lane == 0) {
      int inst = base + i;
      int b = inst >> 12, n = inst & (NN - 1);
      float4 o;
      o.x = s_win[warp][i][16] + tanhf(p0 + ob0);
      o.y = s_win[warp][i][17] + tanhf(p1 + ob1);
      o.z = s_win[warp][i][18] + tanhf(p2 + ob2);
      o.w = s_win[warp][i][19] + tanhf(p3 + ob3);
      *(float4*)&g_win[slot_new][n][b * 4] = o;
      *(float4*)&dout[(size_t)((b * PSTEPS + s) * NN + n) * 4] = o;
    }
  }
}

// ---------------------------------------------------------------------------
extern "C" void kernel_launch(void* const* d_in, const int* in_sizes, int n_in,
                              void* d_out, int out_size) {
  const float* ts     = (const float*)d_in[0];
  const float* A      = (const float*)d_in[1];
  const float* conv_w = (const float*)d_in[2];
  const float* conv_b = (const float*)d_in[3];
  const float* enc_w1 = (const float*)d_in[4];
  const float* enc_w2 = (const float*)d_in[5];
  const float* enc_b  = (const float*)d_in[6];
  const float* dec_w  = (const float*)d_in[7];
  const float* dec_b  = (const float*)d_in[8];
  const float* out_w  = (const float*)d_in[9];
  const float* out_b  = (const float*)d_in[10];
  float* out = (float*)d_out;

  k_init<<<640, 256>>>(ts);
  k_gemm<true><<<EE * 256, 128>>>(A, 0);     // slot 0 + rowsum + node mask
  for (int t = 1; t < TT; t++)
    k_gemm<false><<<EE * 256, 128>>>(A, t);

  for (int s = 0; s < PSTEPS; s++) {
    k_step<<<512, 128>>>(conv_w, conv_b, enc_w1, enc_w2, enc_b,
                         dec_w, dec_b, out_w, out_b, out, s);
    if (s < PSTEPS - 1)
      k_gemm<false><<<EE * 256, 128>>>(A, s % 5);
  }
}